// round 1
// baseline (speedup 1.0000x reference)
#include <cuda_runtime.h>
#include <cuda_bf16.h>
#include <math.h>

// ---------------- problem constants ----------------
#define BB 2
#define TT 2048
#define DD 1024
#define HH 16
#define HD 64
#define NL 6
#define DF 4096
#define NTOK (BB*TT)          // 4096 rows
#define EPSLN 1e-5f

// ---------------- device scratch (no allocs allowed) ----------------
__device__ float g_x   [NTOK*DD];
__device__ float g_xn  [NTOK*DD];
__device__ float g_q   [NTOK*DD];
__device__ float g_k   [NTOK*DD];
__device__ float g_v   [NTOK*DD];
__device__ float g_y   [NTOK*DD];
__device__ float g_xat [NTOK*DD];
__device__ float g_zp  [NTOK*DD];
__device__ float g_rp  [NTOK*DD];
__device__ float g_zs  [NTOK*DD];
__device__ float g_mlp [NTOK*DD];
__device__ float g_h1  [NTOK*DF];
__device__ float g_att [(size_t)BB*HH*TT*TT];   // 536 MB score/prob buffer

// ---------------- small elementwise kernels ----------------
__global__ void copy_kernel(float* __restrict__ dst, const float* __restrict__ src, int n) {
    int i = blockIdx.x * blockDim.x + threadIdx.x;
    if (i < n) dst[i] = src[i];
}

__device__ __forceinline__ float sigmoidf_(float x) { return 1.0f / (1.0f + expf(-x)); }

// x = (1-z)*x + z*tanh(r*x_attn);  store z for reuse
__global__ void gate1_kernel(float* __restrict__ x, const float* __restrict__ xat,
                             const float* __restrict__ zp, const float* __restrict__ rp,
                             float* __restrict__ zs, int n) {
    int i = blockIdx.x * blockDim.x + threadIdx.x;
    if (i >= n) return;
    float z = sigmoidf_(zp[i]);
    float r = sigmoidf_(rp[i]);
    float h = tanhf(r * xat[i]);
    x[i] = (1.0f - z) * x[i] + z * h;
    zs[i] = z;
}

// x = (1-z)*x + z*mlp + src
__global__ void gate2_kernel(float* __restrict__ x, const float* __restrict__ mlp,
                             const float* __restrict__ zs, const float* __restrict__ src, int n) {
    int i = blockIdx.x * blockDim.x + threadIdx.x;
    if (i >= n) return;
    float z = zs[i];
    x[i] = (1.0f - z) * x[i] + z * mlp[i] + src[i];
}

// ---------------- layernorm: one block per row ----------------
__global__ __launch_bounds__(256) void layernorm_kernel(
        const float* __restrict__ x, const float* __restrict__ w,
        const float* __restrict__ b, float* __restrict__ out) {
    int row = blockIdx.x;
    const float* xr = x + (size_t)row * DD;
    float* orow = out + (size_t)row * DD;
    int tid = threadIdx.x;
    __shared__ float s1[256], s2[256];
    float sum = 0.f, ss = 0.f;
    #pragma unroll
    for (int j = tid; j < DD; j += 256) { float v = xr[j]; sum += v; ss += v * v; }
    s1[tid] = sum; s2[tid] = ss;
    __syncthreads();
    for (int s = 128; s > 0; s >>= 1) {
        if (tid < s) { s1[tid] += s1[tid + s]; s2[tid] += s2[tid + s]; }
        __syncthreads();
    }
    float mu = s1[0] * (1.0f / DD);
    float var = s2[0] * (1.0f / DD) - mu * mu;
    float rs = rsqrtf(var + EPSLN);
    for (int j = tid; j < DD; j += 256)
        orow[j] = (xr[j] - mu) * rs * w[j] + b[j];
}

// ---------------- SGEMM: C[M,N] = A[M,K] @ W[K,N] + bias, optional GELU ----------------
// BM=BN=128, BK=16, 256 threads, 8x8 per thread. All dims divisible.
__global__ __launch_bounds__(256) void sgemm_kernel(
        const float* __restrict__ A, const float* __restrict__ W,
        const float* __restrict__ bias, float* __restrict__ C,
        int M, int N, int K, int epi) {
    __shared__ float As[16][128];
    __shared__ float Bs[16][128];
    int tx = threadIdx.x;
    int row0 = blockIdx.y * 128;
    int col0 = blockIdx.x * 128;
    int ty8 = (tx >> 4) * 8;
    int tx8 = (tx & 15) * 8;
    float acc[8][8];
    #pragma unroll
    for (int i = 0; i < 8; i++)
        #pragma unroll
        for (int j = 0; j < 8; j++) acc[i][j] = 0.f;

    int ar = tx >> 2;            // 0..63
    int ac = (tx & 3) * 4;       // 0..12
    int br = tx >> 5;            // 0..7
    int bc = (tx & 31) * 4;      // 0..124

    for (int k0 = 0; k0 < K; k0 += 16) {
        #pragma unroll
        for (int p = 0; p < 2; p++) {
            int r = p * 64 + ar;
            float4 a4 = *(const float4*)(A + (size_t)(row0 + r) * K + k0 + ac);
            As[ac + 0][r] = a4.x; As[ac + 1][r] = a4.y;
            As[ac + 2][r] = a4.z; As[ac + 3][r] = a4.w;
            int kr = p * 8 + br;
            *(float4*)&Bs[kr][bc] = *(const float4*)(W + (size_t)(k0 + kr) * N + col0 + bc);
        }
        __syncthreads();
        #pragma unroll
        for (int kk = 0; kk < 16; kk++) {
            float4 a0 = *(float4*)&As[kk][ty8];
            float4 a1 = *(float4*)&As[kk][ty8 + 4];
            float4 b0 = *(float4*)&Bs[kk][tx8];
            float4 b1 = *(float4*)&Bs[kk][tx8 + 4];
            float a[8] = {a0.x,a0.y,a0.z,a0.w,a1.x,a1.y,a1.z,a1.w};
            float b[8] = {b0.x,b0.y,b0.z,b0.w,b1.x,b1.y,b1.z,b1.w};
            #pragma unroll
            for (int i = 0; i < 8; i++)
                #pragma unroll
                for (int j = 0; j < 8; j++)
                    acc[i][j] = fmaf(a[i], b[j], acc[i][j]);
        }
        __syncthreads();
    }

    #pragma unroll
    for (int i = 0; i < 8; i++) {
        float* crow = C + (size_t)(row0 + ty8 + i) * N + col0 + tx8;
        #pragma unroll
        for (int j = 0; j < 8; j++) {
            float v = acc[i][j] + bias[col0 + tx8 + j];
            if (epi == 1) v = 0.5f * v * (1.0f + erff(v * 0.70710678118654752440f));
            crow[j] = v;
        }
    }
}

// ---------------- attention scores: S = Q @ K^T * scale (lower-tri blocks only) ----------------
// grid: (T/64 cols, T/64 rows, B*H); block 256
__global__ __launch_bounds__(256) void attn_scores_kernel(
        const float* __restrict__ Q, const float* __restrict__ Km,
        float* __restrict__ S, float scale) {
    if (blockIdx.x > blockIdx.y) return;   // fully masked block
    int r0 = blockIdx.y * 64;
    int c0 = blockIdx.x * 64;
    int bh = blockIdx.z;
    int bb = bh / HH, hh = bh % HH;
    const float* qb = Q + (size_t)bb * TT * DD + hh * HD;
    const float* kb = Km + (size_t)bb * TT * DD + hh * HD;
    float* sb = S + (size_t)bh * TT * TT;

    __shared__ float Qs[16][64];
    __shared__ float Ks[16][64];
    int tx = threadIdx.x;
    int lr = tx >> 2;            // 0..63
    int lc = (tx & 3) * 4;       // 0..12
    int ty4 = (tx >> 4) * 4;
    int tx4 = (tx & 15) * 4;
    float acc[4][4];
    #pragma unroll
    for (int i = 0; i < 4; i++)
        #pragma unroll
        for (int j = 0; j < 4; j++) acc[i][j] = 0.f;

    for (int k0 = 0; k0 < HD; k0 += 16) {
        float4 q4 = *(const float4*)(qb + (size_t)(r0 + lr) * DD + k0 + lc);
        Qs[lc + 0][lr] = q4.x; Qs[lc + 1][lr] = q4.y; Qs[lc + 2][lr] = q4.z; Qs[lc + 3][lr] = q4.w;
        float4 k4 = *(const float4*)(kb + (size_t)(c0 + lr) * DD + k0 + lc);
        Ks[lc + 0][lr] = k4.x; Ks[lc + 1][lr] = k4.y; Ks[lc + 2][lr] = k4.z; Ks[lc + 3][lr] = k4.w;
        __syncthreads();
        #pragma unroll
        for (int kk = 0; kk < 16; kk++) {
            float4 a4 = *(float4*)&Qs[kk][ty4];
            float4 b4 = *(float4*)&Ks[kk][tx4];
            float a[4] = {a4.x,a4.y,a4.z,a4.w};
            float b[4] = {b4.x,b4.y,b4.z,b4.w};
            #pragma unroll
            for (int i = 0; i < 4; i++)
                #pragma unroll
                for (int j = 0; j < 4; j++)
                    acc[i][j] = fmaf(a[i], b[j], acc[i][j]);
        }
        __syncthreads();
    }
    #pragma unroll
    for (int i = 0; i < 4; i++) {
        float4 o;
        o.x = acc[i][0] * scale; o.y = acc[i][1] * scale;
        o.z = acc[i][2] * scale; o.w = acc[i][3] * scale;
        *(float4*)(sb + (size_t)(r0 + ty4 + i) * TT + c0 + tx4) = o;
    }
}

// ---------------- causal softmax, in place; zeros masked tail ----------------
// grid: B*H*T rows, block 256
__global__ __launch_bounds__(256) void softmax_kernel(float* __restrict__ S) {
    size_t row = blockIdx.x;
    int qi = (int)(row % TT);
    float* p = S + row * TT;
    int valid = qi + 1;
    int tid = threadIdx.x;
    __shared__ float sred[256];

    float m = -1e30f;
    for (int j = tid; j < valid; j += 256) m = fmaxf(m, p[j]);
    sred[tid] = m; __syncthreads();
    for (int s = 128; s > 0; s >>= 1) {
        if (tid < s) sred[tid] = fmaxf(sred[tid], sred[tid + s]);
        __syncthreads();
    }
    m = sred[0]; __syncthreads();

    float sum = 0.f;
    for (int j = tid; j < valid; j += 256) {
        float e = expf(p[j] - m);
        p[j] = e;
        sum += e;
    }
    sred[tid] = sum; __syncthreads();
    for (int s = 128; s > 0; s >>= 1) {
        if (tid < s) sred[tid] += sred[tid + s];
        __syncthreads();
    }
    float inv = 1.0f / sred[0];
    for (int j = tid; j < valid; j += 256) p[j] *= inv;
    for (int j = valid + tid; j < TT; j += 256) p[j] = 0.f;
}

// ---------------- O = P @ V  (exploits causal zero tail) ----------------
// grid: (T/64, B*H); block 256; out written as [B,T,H,HD]
__global__ __launch_bounds__(256) void attn_av_kernel(
        const float* __restrict__ S, const float* __restrict__ V, float* __restrict__ O) {
    int r0 = blockIdx.x * 64;
    int bh = blockIdx.y;
    int bb = bh / HH, hh = bh % HH;
    const float* sb = S + (size_t)bh * TT * TT;
    const float* vb = V + (size_t)bb * TT * DD + hh * HD;
    float* ob = O + (size_t)bb * TT * DD + hh * HD;

    __shared__ float Ps[32][64];
    __shared__ float Vs[32][64];
    int tx = threadIdx.x;
    int ty4 = (tx >> 4) * 4;
    int tx4 = (tx & 15) * 4;
    float acc[4][4];
    #pragma unroll
    for (int i = 0; i < 4; i++)
        #pragma unroll
        for (int j = 0; j < 4; j++) acc[i][j] = 0.f;

    int kmax = r0 + 64;    // rows beyond query index are zero
    for (int k0 = 0; k0 < kmax; k0 += 32) {
        #pragma unroll
        for (int p = 0; p < 2; p++) {
            int i = p * 32 + (tx >> 3);        // row 0..63
            int c = (tx & 7) * 4;              // k-local 0..28
            float4 p4 = *(const float4*)(sb + (size_t)(r0 + i) * TT + k0 + c);
            Ps[c + 0][i] = p4.x; Ps[c + 1][i] = p4.y; Ps[c + 2][i] = p4.z; Ps[c + 3][i] = p4.w;
            int k = p * 16 + (tx >> 4);        // k-local 0..31
            int d = (tx & 15) * 4;
            *(float4*)&Vs[k][d] = *(const float4*)(vb + (size_t)(k0 + k) * DD + d);
        }
        __syncthreads();
        #pragma unroll
        for (int kk = 0; kk < 32; kk++) {
            float4 a4 = *(float4*)&Ps[kk][ty4];
            float4 b4 = *(float4*)&Vs[kk][tx4];
            float a[4] = {a4.x,a4.y,a4.z,a4.w};
            float b[4] = {b4.x,b4.y,b4.z,b4.w};
            #pragma unroll
            for (int i = 0; i < 4; i++)
                #pragma unroll
                for (int j = 0; j < 4; j++)
                    acc[i][j] = fmaf(a[i], b[j], acc[i][j]);
        }
        __syncthreads();
    }
    #pragma unroll
    for (int i = 0; i < 4; i++) {
        float4 o = {acc[i][0], acc[i][1], acc[i][2], acc[i][3]};
        *(float4*)(ob + (size_t)(r0 + ty4 + i) * DD + tx4) = o;
    }
}

// ---------------- host orchestration ----------------
static float* sym(const void* s) {
    void* p = nullptr;
    cudaGetSymbolAddress(&p, s);
    return (float*)p;
}

extern "C" void kernel_launch(void* const* d_in, const int* in_sizes, int n_in,
                              void* d_out, int out_size) {
    const float* seq  = (const float*)d_in[0];
    const float* Wq   = (const float*)d_in[1];
    const float* bq   = (const float*)d_in[2];
    const float* Wk   = (const float*)d_in[3];
    const float* bk   = (const float*)d_in[4];
    const float* Wv   = (const float*)d_in[5];
    const float* bv   = (const float*)d_in[6];
    const float* Wo   = (const float*)d_in[7];
    const float* bo   = (const float*)d_in[8];
    const float* Wz   = (const float*)d_in[9];
    const float* bz   = (const float*)d_in[10];
    const float* Wr   = (const float*)d_in[11];
    const float* br   = (const float*)d_in[12];
    const float* W1   = (const float*)d_in[13];
    const float* b1   = (const float*)d_in[14];
    const float* W2   = (const float*)d_in[15];
    const float* b2   = (const float*)d_in[16];
    const float* ln1w = (const float*)d_in[17];
    const float* ln1b = (const float*)d_in[18];
    const float* ln2w = (const float*)d_in[19];
    const float* ln2b = (const float*)d_in[20];
    const float* lnfw = (const float*)d_in[21];
    const float* lnfb = (const float*)d_in[22];

    float* x   = sym(g_x);
    float* xn  = sym(g_xn);
    float* q   = sym(g_q);
    float* k   = sym(g_k);
    float* v   = sym(g_v);
    float* y   = sym(g_y);
    float* xat = sym(g_xat);
    float* zp  = sym(g_zp);
    float* rp  = sym(g_rp);
    float* zs  = sym(g_zs);
    float* mlp = sym(g_mlp);
    float* h1  = sym(g_h1);
    float* att = sym(g_att);

    const int nElem = NTOK * DD;
    const int ethreads = 256;
    const int eblocks = (nElem + ethreads - 1) / ethreads;
    const float scale = 0.125f;   // 1/sqrt(64)

    copy_kernel<<<eblocks, ethreads>>>(x, seq, nElem);

    dim3 gD(DD / 128, NTOK / 128);     // (8, 32)
    dim3 gF(DF / 128, NTOK / 128);     // (32, 32)
    dim3 gS(TT / 64, TT / 64, BB * HH);
    dim3 gA(TT / 64, BB * HH);

    for (int l = 0; l < NL; l++) {
        const float* wq = Wq + (size_t)l * DD * DD;
        const float* wk = Wk + (size_t)l * DD * DD;
        const float* wv = Wv + (size_t)l * DD * DD;
        const float* wo = Wo + (size_t)l * DD * DD;
        const float* wz = Wz + (size_t)l * DD * DD;
        const float* wr = Wr + (size_t)l * DD * DD;
        const float* w1 = W1 + (size_t)l * DD * DF;
        const float* w2 = W2 + (size_t)l * DF * DD;

        layernorm_kernel<<<NTOK, 256>>>(x, ln1w + l * DD, ln1b + l * DD, xn);

        sgemm_kernel<<<gD, 256>>>(xn, wq, bq + l * DD, q, NTOK, DD, DD, 0);
        sgemm_kernel<<<gD, 256>>>(xn, wk, bk + l * DD, k, NTOK, DD, DD, 0);
        sgemm_kernel<<<gD, 256>>>(xn, wv, bv + l * DD, v, NTOK, DD, DD, 0);
        sgemm_kernel<<<gD, 256>>>(xn, wz, bz + l * DD, zp, NTOK, DD, DD, 0);
        sgemm_kernel<<<gD, 256>>>(xn, wr, br + l * DD, rp, NTOK, DD, DD, 0);

        attn_scores_kernel<<<gS, 256>>>(q, k, att, scale);
        softmax_kernel<<<BB * HH * TT, 256>>>(att);
        attn_av_kernel<<<gA, 256>>>(att, v, y);

        sgemm_kernel<<<gD, 256>>>(y, wo, bo + l * DD, xat, NTOK, DD, DD, 0);
        gate1_kernel<<<eblocks, ethreads>>>(x, xat, zp, rp, zs, nElem);

        layernorm_kernel<<<NTOK, 256>>>(x, ln2w + l * DD, ln2b + l * DD, xn);
        sgemm_kernel<<<gF, 256>>>(xn, w1, b1 + l * DF, h1, NTOK, DF, DD, 1);   // +GELU
        sgemm_kernel<<<gD, 256>>>(h1, w2, b2 + l * DD, mlp, NTOK, DD, DF, 0);
        gate2_kernel<<<eblocks, ethreads>>>(x, mlp, zs, seq, nElem);
    }

    layernorm_kernel<<<NTOK, 256>>>(x, lnfw, lnfb, (float*)d_out);
}

// round 2
// speedup vs baseline: 2.0807x; 2.0807x over previous
#include <cuda_runtime.h>
#include <cuda_bf16.h>
#include <math.h>
#include <stdint.h>

// ---------------- problem constants ----------------
#define BB 2
#define TT 2048
#define DD 1024
#define HH 16
#define HD 64
#define NL 6
#define DF 4096
#define NTOK (BB*TT)          // 4096 rows
#define QKVLD 5120            // fused QKVZR row stride
#define EPSLN 1e-5f

// ---------------- device scratch (no allocs allowed) ----------------
__device__ float g_x    [NTOK*DD];
__device__ float g_xn   [NTOK*DD];
__device__ float g_qkvzr[NTOK*QKVLD];   // q|k|v|zp|rp fused, 84MB
__device__ float g_y    [NTOK*DD];
__device__ float g_xat  [NTOK*DD];
__device__ float g_zs   [NTOK*DD];
__device__ float g_mlp  [NTOK*DD];
__device__ float g_h1   [NTOK*DF];
__device__ float g_att  [(size_t)BB*HH*TT*TT];   // 536 MB score/prob buffer

// ---------------- helpers ----------------
__device__ __forceinline__ float tf32r(float x) {
    uint32_t u;
    asm("cvt.rna.tf32.f32 %0, %1;" : "=r"(u) : "f"(x));
    return __uint_as_float(u);
}

__device__ __forceinline__ void mma_tf32(float* d, const uint32_t* a, const uint32_t* b) {
    asm volatile(
        "mma.sync.aligned.m16n8k8.row.col.f32.tf32.tf32.f32 "
        "{%0,%1,%2,%3}, {%4,%5,%6,%7}, {%8,%9}, {%0,%1,%2,%3};"
        : "+f"(d[0]), "+f"(d[1]), "+f"(d[2]), "+f"(d[3])
        : "r"(a[0]), "r"(a[1]), "r"(a[2]), "r"(a[3]),
          "r"(b[0]), "r"(b[1]));
}

__device__ __forceinline__ float sigmoidf_(float x) { return 1.0f / (1.0f + expf(-x)); }

// ---------------- small elementwise kernels ----------------
__global__ void copy_kernel(float* __restrict__ dst, const float* __restrict__ src, int n) {
    int i = blockIdx.x * blockDim.x + threadIdx.x;
    if (i < n) dst[i] = src[i];
}

// x = (1-z)*x + z*tanh(r*x_attn); store z. zp/rp live in fused buffer (stride QKVLD)
__global__ void gate1_kernel(float* __restrict__ x, const float* __restrict__ xat,
                             const float* __restrict__ qkvzr, float* __restrict__ zs, int n) {
    int i = blockIdx.x * blockDim.x + threadIdx.x;
    if (i >= n) return;
    int row = i >> 10;          // /1024
    int col = i & 1023;
    size_t base = (size_t)row * QKVLD + col;
    float z = sigmoidf_(qkvzr[base + 3072]);
    float r = sigmoidf_(qkvzr[base + 4096]);
    float h = tanhf(r * xat[i]);
    x[i] = (1.0f - z) * x[i] + z * h;
    zs[i] = z;
}

// x = (1-z)*x + z*mlp + src
__global__ void gate2_kernel(float* __restrict__ x, const float* __restrict__ mlp,
                             const float* __restrict__ zs, const float* __restrict__ src, int n) {
    int i = blockIdx.x * blockDim.x + threadIdx.x;
    if (i >= n) return;
    float z = zs[i];
    x[i] = (1.0f - z) * x[i] + z * mlp[i] + src[i];
}

// ---------------- layernorm: one block per row ----------------
__global__ __launch_bounds__(256) void layernorm_kernel(
        const float* __restrict__ x, const float* __restrict__ w,
        const float* __restrict__ b, float* __restrict__ out) {
    int row = blockIdx.x;
    const float* xr = x + (size_t)row * DD;
    float* orow = out + (size_t)row * DD;
    int tid = threadIdx.x;
    __shared__ float s1[256], s2[256];
    float sum = 0.f, ss = 0.f;
    #pragma unroll
    for (int j = tid; j < DD; j += 256) { float v = xr[j]; sum += v; ss += v * v; }
    s1[tid] = sum; s2[tid] = ss;
    __syncthreads();
    for (int s = 128; s > 0; s >>= 1) {
        if (tid < s) { s1[tid] += s1[tid + s]; s2[tid] += s2[tid + s]; }
        __syncthreads();
    }
    float mu = s1[0] * (1.0f / DD);
    float var = s2[0] * (1.0f / DD) - mu * mu;
    float rs = rsqrtf(var + EPSLN);
    for (int j = tid; j < DD; j += 256)
        orow[j] = (xr[j] - mu) * rs * w[j] + b[j];
}

// ---------------- TF32 tensor-core GEMM ----------------
// C[M, nmat*N] = A[M,K] @ {W_i[K,N]} + bias_i, per-matrix column blocks.
// BM=BN=128, BK=16, 256 threads (8 warps, 2x4 warp grid, 64x32 warp tiles).
// epi: 0=none, 1=exact GELU
struct GemmArgs {
    const float* w[5];
    const float* bias[5];
};

#define APAD 20     // A smem row pitch (floats)
#define BPAD 136    // B smem row pitch (floats)

__global__ __launch_bounds__(256) void gemm_tf32_kernel(
        const float* __restrict__ A, GemmArgs args, float* __restrict__ C,
        int K, int nblkPerMat, int ldW, int ldC, int epi) {
    __shared__ float As[2][128 * APAD];
    __shared__ float Bs[2][16 * BPAD];

    const int tx   = threadIdx.x;
    const int warp = tx >> 5;
    const int lane = tx & 31;
    const int g    = lane >> 2;     // group id 0..7
    const int tg   = lane & 3;      // thread-in-group 0..3

    const int bx   = blockIdx.x;
    const int wi   = bx / nblkPerMat;
    const int bxl  = bx - wi * nblkPerMat;
    const float* W    = args.w[wi];
    const float* bias = args.bias[wi];

    const int row0  = blockIdx.y * 128;
    const int wcol0 = bxl * 128;       // column within this W matrix
    const int ocol0 = bx * 128;        // column within output C

    const int wm = (warp >> 2) * 64;   // warp row offset   (0 or 64)
    const int wn = (warp & 3) * 32;    // warp col offset   (0,32,64,96)

    // global-load coordinates
    const int ar = tx >> 2;            // 0..63
    const int ac = (tx & 3) * 4;       // 0,4,8,12
    const int br = tx >> 5;            // 0..7
    const int bc = (tx & 31) * 4;      // 0..124

    float acc[4][4][4];
    #pragma unroll
    for (int i = 0; i < 4; i++)
        #pragma unroll
        for (int j = 0; j < 4; j++)
            #pragma unroll
            for (int c = 0; c < 4; c++) acc[i][j][c] = 0.f;

    float4 ra0, ra1, rb0, rb1;

    auto loadG = [&](int k0) {
        ra0 = *(const float4*)(A + (size_t)(row0 + ar) * K + k0 + ac);
        ra1 = *(const float4*)(A + (size_t)(row0 + ar + 64) * K + k0 + ac);
        rb0 = *(const float4*)(W + (size_t)(k0 + br) * ldW + wcol0 + bc);
        rb1 = *(const float4*)(W + (size_t)(k0 + br + 8) * ldW + wcol0 + bc);
    };
    auto storeS = [&](int buf) {
        float* ap = &As[buf][ar * APAD + ac];
        ap[0] = tf32r(ra0.x); ap[1] = tf32r(ra0.y); ap[2] = tf32r(ra0.z); ap[3] = tf32r(ra0.w);
        ap = &As[buf][(ar + 64) * APAD + ac];
        ap[0] = tf32r(ra1.x); ap[1] = tf32r(ra1.y); ap[2] = tf32r(ra1.z); ap[3] = tf32r(ra1.w);
        float* bp = &Bs[buf][br * BPAD + bc];
        bp[0] = tf32r(rb0.x); bp[1] = tf32r(rb0.y); bp[2] = tf32r(rb0.z); bp[3] = tf32r(rb0.w);
        bp = &Bs[buf][(br + 8) * BPAD + bc];
        bp[0] = tf32r(rb1.x); bp[1] = tf32r(rb1.y); bp[2] = tf32r(rb1.z); bp[3] = tf32r(rb1.w);
    };

    loadG(0);
    storeS(0);
    __syncthreads();

    const int nk = K >> 4;
    for (int kt = 0; kt < nk; kt++) {
        const int cur = kt & 1;
        const bool more = (kt + 1 < nk);
        if (more) loadG((kt + 1) << 4);

        const float* Ab = &As[cur][0];
        const float* Bb = &Bs[cur][0];
        #pragma unroll
        for (int ks = 0; ks < 2; ks++) {
            const int kc = ks * 8;
            uint32_t af[4][4];
            uint32_t bf[4][2];
            #pragma unroll
            for (int fm = 0; fm < 4; fm++) {
                int r = wm + fm * 16 + g;
                af[fm][0] = __float_as_uint(Ab[r * APAD + kc + tg]);
                af[fm][1] = __float_as_uint(Ab[(r + 8) * APAD + kc + tg]);
                af[fm][2] = __float_as_uint(Ab[r * APAD + kc + tg + 4]);
                af[fm][3] = __float_as_uint(Ab[(r + 8) * APAD + kc + tg + 4]);
            }
            #pragma unroll
            for (int fn = 0; fn < 4; fn++) {
                int c = wn + fn * 8 + g;
                bf[fn][0] = __float_as_uint(Bb[(kc + tg) * BPAD + c]);
                bf[fn][1] = __float_as_uint(Bb[(kc + tg + 4) * BPAD + c]);
            }
            #pragma unroll
            for (int fm = 0; fm < 4; fm++)
                #pragma unroll
                for (int fn = 0; fn < 4; fn++)
                    mma_tf32(acc[fm][fn], af[fm], bf[fn]);
        }

        if (more) {
            storeS(cur ^ 1);
            __syncthreads();
        }
    }

    // epilogue: bias (+ optional GELU), float2 stores
    #pragma unroll
    for (int fm = 0; fm < 4; fm++) {
        int r1 = row0 + wm + fm * 16 + g;
        #pragma unroll
        for (int fn = 0; fn < 4; fn++) {
            int cl = wn + fn * 8 + tg * 2;
            float bz0 = bias[wcol0 + cl];
            float bz1 = bias[wcol0 + cl + 1];
            float v00 = acc[fm][fn][0] + bz0;
            float v01 = acc[fm][fn][1] + bz1;
            float v10 = acc[fm][fn][2] + bz0;
            float v11 = acc[fm][fn][3] + bz1;
            if (epi == 1) {
                v00 = 0.5f * v00 * (1.0f + erff(v00 * 0.70710678118654752440f));
                v01 = 0.5f * v01 * (1.0f + erff(v01 * 0.70710678118654752440f));
                v10 = 0.5f * v10 * (1.0f + erff(v10 * 0.70710678118654752440f));
                v11 = 0.5f * v11 * (1.0f + erff(v11 * 0.70710678118654752440f));
            }
            float2 o0 = {v00, v01};
            float2 o1 = {v10, v11};
            *(float2*)(C + (size_t)r1 * ldC + ocol0 + cl) = o0;
            *(float2*)(C + (size_t)(r1 + 8) * ldC + ocol0 + cl) = o1;
        }
    }
}

// ---------------- attention scores: S = Q @ K^T * scale (lower-tri blocks) ----------------
__global__ __launch_bounds__(256) void attn_scores_kernel(
        const float* __restrict__ Q, const float* __restrict__ Km,
        float* __restrict__ S, float scale, int ldq) {
    if (blockIdx.x > blockIdx.y) return;
    int r0 = blockIdx.y * 64;
    int c0 = blockIdx.x * 64;
    int bh = blockIdx.z;
    int bb = bh / HH, hh = bh % HH;
    const float* qb = Q + (size_t)bb * TT * ldq + hh * HD;
    const float* kb = Km + (size_t)bb * TT * ldq + hh * HD;
    float* sb = S + (size_t)bh * TT * TT;

    __shared__ float Qs[16][64];
    __shared__ float Ks[16][64];
    int tx = threadIdx.x;
    int lr = tx >> 2;
    int lc = (tx & 3) * 4;
    int ty4 = (tx >> 4) * 4;
    int tx4 = (tx & 15) * 4;
    float acc[4][4];
    #pragma unroll
    for (int i = 0; i < 4; i++)
        #pragma unroll
        for (int j = 0; j < 4; j++) acc[i][j] = 0.f;

    for (int k0 = 0; k0 < HD; k0 += 16) {
        float4 q4 = *(const float4*)(qb + (size_t)(r0 + lr) * ldq + k0 + lc);
        Qs[lc + 0][lr] = q4.x; Qs[lc + 1][lr] = q4.y; Qs[lc + 2][lr] = q4.z; Qs[lc + 3][lr] = q4.w;
        float4 k4 = *(const float4*)(kb + (size_t)(c0 + lr) * ldq + k0 + lc);
        Ks[lc + 0][lr] = k4.x; Ks[lc + 1][lr] = k4.y; Ks[lc + 2][lr] = k4.z; Ks[lc + 3][lr] = k4.w;
        __syncthreads();
        #pragma unroll
        for (int kk = 0; kk < 16; kk++) {
            float4 a4 = *(float4*)&Qs[kk][ty4];
            float4 b4 = *(float4*)&Ks[kk][tx4];
            float a[4] = {a4.x,a4.y,a4.z,a4.w};
            float b[4] = {b4.x,b4.y,b4.z,b4.w};
            #pragma unroll
            for (int i = 0; i < 4; i++)
                #pragma unroll
                for (int j = 0; j < 4; j++)
                    acc[i][j] = fmaf(a[i], b[j], acc[i][j]);
        }
        __syncthreads();
    }
    #pragma unroll
    for (int i = 0; i < 4; i++) {
        float4 o;
        o.x = acc[i][0] * scale; o.y = acc[i][1] * scale;
        o.z = acc[i][2] * scale; o.w = acc[i][3] * scale;
        *(float4*)(sb + (size_t)(r0 + ty4 + i) * TT + c0 + tx4) = o;
    }
}

// ---------------- causal softmax, in place; zeros masked tail ----------------
__global__ __launch_bounds__(256) void softmax_kernel(float* __restrict__ S) {
    size_t row = blockIdx.x;
    int qi = (int)(row % TT);
    float* p = S + row * TT;
    int valid = qi + 1;
    int tid = threadIdx.x;
    __shared__ float sred[256];

    float m = -1e30f;
    for (int j = tid; j < valid; j += 256) m = fmaxf(m, p[j]);
    sred[tid] = m; __syncthreads();
    for (int s = 128; s > 0; s >>= 1) {
        if (tid < s) sred[tid] = fmaxf(sred[tid], sred[tid + s]);
        __syncthreads();
    }
    m = sred[0]; __syncthreads();

    float sum = 0.f;
    for (int j = tid; j < valid; j += 256) {
        float e = expf(p[j] - m);
        p[j] = e;
        sum += e;
    }
    sred[tid] = sum; __syncthreads();
    for (int s = 128; s > 0; s >>= 1) {
        if (tid < s) sred[tid] += sred[tid + s];
        __syncthreads();
    }
    float inv = 1.0f / sred[0];
    for (int j = tid; j < valid; j += 256) p[j] *= inv;
    for (int j = valid + tid; j < TT; j += 256) p[j] = 0.f;
}

// ---------------- O = P @ V ----------------
__global__ __launch_bounds__(256) void attn_av_kernel(
        const float* __restrict__ S, const float* __restrict__ V,
        float* __restrict__ O, int ldv) {
    int r0 = blockIdx.x * 64;
    int bh = blockIdx.y;
    int bb = bh / HH, hh = bh % HH;
    const float* sb = S + (size_t)bh * TT * TT;
    const float* vb = V + (size_t)bb * TT * ldv + hh * HD;
    float* ob = O + (size_t)bb * TT * DD + hh * HD;

    __shared__ float Ps[32][64];
    __shared__ float Vs[32][64];
    int tx = threadIdx.x;
    int ty4 = (tx >> 4) * 4;
    int tx4 = (tx & 15) * 4;
    float acc[4][4];
    #pragma unroll
    for (int i = 0; i < 4; i++)
        #pragma unroll
        for (int j = 0; j < 4; j++) acc[i][j] = 0.f;

    int kmax = r0 + 64;
    for (int k0 = 0; k0 < kmax; k0 += 32) {
        #pragma unroll
        for (int p = 0; p < 2; p++) {
            int i = p * 32 + (tx >> 3);
            int c = (tx & 7) * 4;
            float4 p4 = *(const float4*)(sb + (size_t)(r0 + i) * TT + k0 + c);
            Ps[c + 0][i] = p4.x; Ps[c + 1][i] = p4.y; Ps[c + 2][i] = p4.z; Ps[c + 3][i] = p4.w;
            int k = p * 16 + (tx >> 4);
            int d = (tx & 15) * 4;
            *(float4*)&Vs[k][d] = *(const float4*)(vb + (size_t)(k0 + k) * ldv + d);
        }
        __syncthreads();
        #pragma unroll
        for (int kk = 0; kk < 32; kk++) {
            float4 a4 = *(float4*)&Ps[kk][ty4];
            float4 b4 = *(float4*)&Vs[kk][tx4];
            float a[4] = {a4.x,a4.y,a4.z,a4.w};
            float b[4] = {b4.x,b4.y,b4.z,b4.w};
            #pragma unroll
            for (int i = 0; i < 4; i++)
                #pragma unroll
                for (int j = 0; j < 4; j++)
                    acc[i][j] = fmaf(a[i], b[j], acc[i][j]);
        }
        __syncthreads();
    }
    #pragma unroll
    for (int i = 0; i < 4; i++) {
        float4 o = {acc[i][0], acc[i][1], acc[i][2], acc[i][3]};
        *(float4*)(ob + (size_t)(r0 + ty4 + i) * DD + tx4) = o;
    }
}

// ---------------- host orchestration ----------------
static float* sym(const void* s) {
    void* p = nullptr;
    cudaGetSymbolAddress(&p, s);
    return (float*)p;
}

extern "C" void kernel_launch(void* const* d_in, const int* in_sizes, int n_in,
                              void* d_out, int out_size) {
    const float* seq  = (const float*)d_in[0];
    const float* Wq   = (const float*)d_in[1];
    const float* bq   = (const float*)d_in[2];
    const float* Wk   = (const float*)d_in[3];
    const float* bk   = (const float*)d_in[4];
    const float* Wv   = (const float*)d_in[5];
    const float* bv   = (const float*)d_in[6];
    const float* Wo   = (const float*)d_in[7];
    const float* bo   = (const float*)d_in[8];
    const float* Wz   = (const float*)d_in[9];
    const float* bz   = (const float*)d_in[10];
    const float* Wr   = (const float*)d_in[11];
    const float* br   = (const float*)d_in[12];
    const float* W1   = (const float*)d_in[13];
    const float* b1   = (const float*)d_in[14];
    const float* W2   = (const float*)d_in[15];
    const float* b2   = (const float*)d_in[16];
    const float* ln1w = (const float*)d_in[17];
    const float* ln1b = (const float*)d_in[18];
    const float* ln2w = (const float*)d_in[19];
    const float* ln2b = (const float*)d_in[20];
    const float* lnfw = (const float*)d_in[21];
    const float* lnfb = (const float*)d_in[22];

    float* x     = sym(g_x);
    float* xn    = sym(g_xn);
    float* qkvzr = sym(g_qkvzr);
    float* y     = sym(g_y);
    float* xat   = sym(g_xat);
    float* zs    = sym(g_zs);
    float* mlp   = sym(g_mlp);
    float* h1    = sym(g_h1);
    float* att   = sym(g_att);

    const int nElem = NTOK * DD;
    const int ethreads = 256;
    const int eblocks = (nElem + ethreads - 1) / ethreads;
    const float scale = 0.125f;   // 1/sqrt(64)

    copy_kernel<<<eblocks, ethreads>>>(x, seq, nElem);

    dim3 gQKVZR(40, 32);   // 5 matrices x 8 col-blocks, 32 row-blocks
    dim3 gD(8, 32);
    dim3 gF(32, 32);
    dim3 gS(TT / 64, TT / 64, BB * HH);
    dim3 gA(TT / 64, BB * HH);

    for (int l = 0; l < NL; l++) {
        GemmArgs a5, a1, aw1, aw2;
        a5.w[0] = Wq + (size_t)l * DD * DD;  a5.bias[0] = bq + l * DD;
        a5.w[1] = Wk + (size_t)l * DD * DD;  a5.bias[1] = bk + l * DD;
        a5.w[2] = Wv + (size_t)l * DD * DD;  a5.bias[2] = bv + l * DD;
        a5.w[3] = Wz + (size_t)l * DD * DD;  a5.bias[3] = bz + l * DD;
        a5.w[4] = Wr + (size_t)l * DD * DD;  a5.bias[4] = br + l * DD;
        a1.w[0] = Wo + (size_t)l * DD * DD;  a1.bias[0] = bo + l * DD;
        for (int j = 1; j < 5; j++) { a1.w[j] = a1.w[0]; a1.bias[j] = a1.bias[0]; }
        aw1.w[0] = W1 + (size_t)l * DD * DF; aw1.bias[0] = b1 + l * DF;
        for (int j = 1; j < 5; j++) { aw1.w[j] = aw1.w[0]; aw1.bias[j] = aw1.bias[0]; }
        aw2.w[0] = W2 + (size_t)l * DF * DD; aw2.bias[0] = b2 + l * DD;
        for (int j = 1; j < 5; j++) { aw2.w[j] = aw2.w[0]; aw2.bias[j] = aw2.bias[0]; }

        layernorm_kernel<<<NTOK, 256>>>(x, ln1w + l * DD, ln1b + l * DD, xn);

        // fused Q,K,V,Z,R projections -> qkvzr [NTOK, 5120]
        gemm_tf32_kernel<<<gQKVZR, 256>>>(xn, a5, qkvzr, DD, 8, DD, QKVLD, 0);

        attn_scores_kernel<<<gS, 256>>>(qkvzr + 0, qkvzr + 1024, att, scale, QKVLD);
        softmax_kernel<<<BB * HH * TT, 256>>>(att);
        attn_av_kernel<<<gA, 256>>>(att, qkvzr + 2048, y, QKVLD);

        gemm_tf32_kernel<<<gD, 256>>>(y, a1, xat, DD, 8, DD, DD, 0);
        gate1_kernel<<<eblocks, ethreads>>>(x, xat, qkvzr, zs, nElem);

        layernorm_kernel<<<NTOK, 256>>>(x, ln2w + l * DD, ln2b + l * DD, xn);
        gemm_tf32_kernel<<<gF, 256>>>(xn, aw1, h1, DD, 32, DF, DF, 1);   // +GELU
        gemm_tf32_kernel<<<gD, 256>>>(h1, aw2, mlp, DF, 8, DD, DD, 0);
        gate2_kernel<<<eblocks, ethreads>>>(x, mlp, zs, seq, nElem);
    }

    layernorm_kernel<<<NTOK, 256>>>(x, lnfw, lnfb, (float*)d_out);
}

// round 3
// speedup vs baseline: 3.0798x; 1.4801x over previous
#include <cuda_runtime.h>
#include <cuda_bf16.h>
#include <math.h>
#include <stdint.h>

// ---------------- problem constants ----------------
#define BB 2
#define TT 2048
#define DD 1024
#define HH 16
#define HD 64
#define NL 6
#define DF 4096
#define NTOK (BB*TT)          // 4096 rows
#define QKVLD 5120            // fused QKVZR row stride
#define EPSLN 1e-5f

// ---------------- device scratch (no allocs allowed) ----------------
__device__ float g_x    [NTOK*DD];
__device__ float g_xn   [NTOK*DD];
__device__ float g_qkvzr[NTOK*QKVLD];   // q|k|v|zp|rp fused, 84MB
__device__ float g_y    [NTOK*DD];
__device__ float g_xat  [NTOK*DD];
__device__ float g_zs   [NTOK*DD];
__device__ float g_mlp  [NTOK*DD];
__device__ float g_h1   [NTOK*DF];

// ---------------- helpers ----------------
__device__ __forceinline__ float tf32r(float x) {
    uint32_t u;
    asm("cvt.rna.tf32.f32 %0, %1;" : "=r"(u) : "f"(x));
    return __uint_as_float(u);
}

__device__ __forceinline__ float exp2a(float x) {
    float y;
    asm("ex2.approx.f32 %0, %1;" : "=f"(y) : "f"(x));
    return y;
}

__device__ __forceinline__ void mma_tf32(float* d, const uint32_t* a, const uint32_t* b) {
    asm volatile(
        "mma.sync.aligned.m16n8k8.row.col.f32.tf32.tf32.f32 "
        "{%0,%1,%2,%3}, {%4,%5,%6,%7}, {%8,%9}, {%0,%1,%2,%3};"
        : "+f"(d[0]), "+f"(d[1]), "+f"(d[2]), "+f"(d[3])
        : "r"(a[0]), "r"(a[1]), "r"(a[2]), "r"(a[3]),
          "r"(b[0]), "r"(b[1]));
}

__device__ __forceinline__ float sigmoidf_(float x) { return 1.0f / (1.0f + expf(-x)); }

// ---------------- small elementwise kernels ----------------
__global__ void copy_kernel(float* __restrict__ dst, const float* __restrict__ src, int n) {
    int i = blockIdx.x * blockDim.x + threadIdx.x;
    if (i < n) dst[i] = src[i];
}

// x = (1-z)*x + z*tanh(r*x_attn); store z. zp/rp live in fused buffer (stride QKVLD)
__global__ void gate1_kernel(float* __restrict__ x, const float* __restrict__ xat,
                             const float* __restrict__ qkvzr, float* __restrict__ zs, int n) {
    int i = blockIdx.x * blockDim.x + threadIdx.x;
    if (i >= n) return;
    int row = i >> 10;
    int col = i & 1023;
    size_t base = (size_t)row * QKVLD + col;
    float z = sigmoidf_(qkvzr[base + 3072]);
    float r = sigmoidf_(qkvzr[base + 4096]);
    float h = tanhf(r * xat[i]);
    x[i] = (1.0f - z) * x[i] + z * h;
    zs[i] = z;
}

// x = (1-z)*x + z*mlp + src
__global__ void gate2_kernel(float* __restrict__ x, const float* __restrict__ mlp,
                             const float* __restrict__ zs, const float* __restrict__ src, int n) {
    int i = blockIdx.x * blockDim.x + threadIdx.x;
    if (i >= n) return;
    float z = zs[i];
    x[i] = (1.0f - z) * x[i] + z * mlp[i] + src[i];
}

// ---------------- layernorm: one block per row ----------------
__global__ __launch_bounds__(256) void layernorm_kernel(
        const float* __restrict__ x, const float* __restrict__ w,
        const float* __restrict__ b, float* __restrict__ out) {
    int row = blockIdx.x;
    const float* xr = x + (size_t)row * DD;
    float* orow = out + (size_t)row * DD;
    int tid = threadIdx.x;
    __shared__ float s1[256], s2[256];
    float sum = 0.f, ss = 0.f;
    #pragma unroll
    for (int j = tid; j < DD; j += 256) { float v = xr[j]; sum += v; ss += v * v; }
    s1[tid] = sum; s2[tid] = ss;
    __syncthreads();
    for (int s = 128; s > 0; s >>= 1) {
        if (tid < s) { s1[tid] += s1[tid + s]; s2[tid] += s2[tid + s]; }
        __syncthreads();
    }
    float mu = s1[0] * (1.0f / DD);
    float var = s2[0] * (1.0f / DD) - mu * mu;
    float rs = rsqrtf(var + EPSLN);
    for (int j = tid; j < DD; j += 256)
        orow[j] = (xr[j] - mu) * rs * w[j] + b[j];
}

// ---------------- TF32 tensor-core GEMM ----------------
struct GemmArgs {
    const float* w[5];
    const float* bias[5];
};

#define APAD 20     // A smem row pitch (floats)
#define BPAD 136    // B smem row pitch (floats)

__global__ __launch_bounds__(256) void gemm_tf32_kernel(
        const float* __restrict__ A, GemmArgs args, float* __restrict__ C,
        int K, int nblkPerMat, int ldW, int ldC, int epi) {
    __shared__ float As[2][128 * APAD];
    __shared__ float Bs[2][16 * BPAD];

    const int tx   = threadIdx.x;
    const int warp = tx >> 5;
    const int lane = tx & 31;
    const int g    = lane >> 2;
    const int tg   = lane & 3;

    const int bx   = blockIdx.x;
    const int wi   = bx / nblkPerMat;
    const int bxl  = bx - wi * nblkPerMat;
    const float* W    = args.w[wi];
    const float* bias = args.bias[wi];

    const int row0  = blockIdx.y * 128;
    const int wcol0 = bxl * 128;
    const int ocol0 = bx * 128;

    const int wm = (warp >> 2) * 64;
    const int wn = (warp & 3) * 32;

    const int ar = tx >> 2;
    const int ac = (tx & 3) * 4;
    const int br = tx >> 5;
    const int bc = (tx & 31) * 4;

    float acc[4][4][4];
    #pragma unroll
    for (int i = 0; i < 4; i++)
        #pragma unroll
        for (int j = 0; j < 4; j++)
            #pragma unroll
            for (int c = 0; c < 4; c++) acc[i][j][c] = 0.f;

    float4 ra0, ra1, rb0, rb1;

    auto loadG = [&](int k0) {
        ra0 = *(const float4*)(A + (size_t)(row0 + ar) * K + k0 + ac);
        ra1 = *(const float4*)(A + (size_t)(row0 + ar + 64) * K + k0 + ac);
        rb0 = *(const float4*)(W + (size_t)(k0 + br) * ldW + wcol0 + bc);
        rb1 = *(const float4*)(W + (size_t)(k0 + br + 8) * ldW + wcol0 + bc);
    };
    auto storeS = [&](int buf) {
        float* ap = &As[buf][ar * APAD + ac];
        ap[0] = tf32r(ra0.x); ap[1] = tf32r(ra0.y); ap[2] = tf32r(ra0.z); ap[3] = tf32r(ra0.w);
        ap = &As[buf][(ar + 64) * APAD + ac];
        ap[0] = tf32r(ra1.x); ap[1] = tf32r(ra1.y); ap[2] = tf32r(ra1.z); ap[3] = tf32r(ra1.w);
        float* bp = &Bs[buf][br * BPAD + bc];
        bp[0] = tf32r(rb0.x); bp[1] = tf32r(rb0.y); bp[2] = tf32r(rb0.z); bp[3] = tf32r(rb0.w);
        bp = &Bs[buf][(br + 8) * BPAD + bc];
        bp[0] = tf32r(rb1.x); bp[1] = tf32r(rb1.y); bp[2] = tf32r(rb1.z); bp[3] = tf32r(rb1.w);
    };

    loadG(0);
    storeS(0);
    __syncthreads();

    const int nk = K >> 4;
    for (int kt = 0; kt < nk; kt++) {
        const int cur = kt & 1;
        const bool more = (kt + 1 < nk);
        if (more) loadG((kt + 1) << 4);

        const float* Ab = &As[cur][0];
        const float* Bb = &Bs[cur][0];
        #pragma unroll
        for (int ks = 0; ks < 2; ks++) {
            const int kc = ks * 8;
            uint32_t af[4][4];
            uint32_t bf[4][2];
            #pragma unroll
            for (int fm = 0; fm < 4; fm++) {
                int r = wm + fm * 16 + g;
                af[fm][0] = __float_as_uint(Ab[r * APAD + kc + tg]);
                af[fm][1] = __float_as_uint(Ab[(r + 8) * APAD + kc + tg]);
                af[fm][2] = __float_as_uint(Ab[r * APAD + kc + tg + 4]);
                af[fm][3] = __float_as_uint(Ab[(r + 8) * APAD + kc + tg + 4]);
            }
            #pragma unroll
            for (int fn = 0; fn < 4; fn++) {
                int c = wn + fn * 8 + g;
                bf[fn][0] = __float_as_uint(Bb[(kc + tg) * BPAD + c]);
                bf[fn][1] = __float_as_uint(Bb[(kc + tg + 4) * BPAD + c]);
            }
            #pragma unroll
            for (int fm = 0; fm < 4; fm++)
                #pragma unroll
                for (int fn = 0; fn < 4; fn++)
                    mma_tf32(acc[fm][fn], af[fm], bf[fn]);
        }

        if (more) {
            storeS(cur ^ 1);
            __syncthreads();
        }
    }

    #pragma unroll
    for (int fm = 0; fm < 4; fm++) {
        int r1 = row0 + wm + fm * 16 + g;
        #pragma unroll
        for (int fn = 0; fn < 4; fn++) {
            int cl = wn + fn * 8 + tg * 2;
            float bz0 = bias[wcol0 + cl];
            float bz1 = bias[wcol0 + cl + 1];
            float v00 = acc[fm][fn][0] + bz0;
            float v01 = acc[fm][fn][1] + bz1;
            float v10 = acc[fm][fn][2] + bz0;
            float v11 = acc[fm][fn][3] + bz1;
            if (epi == 1) {
                v00 = 0.5f * v00 * (1.0f + erff(v00 * 0.70710678118654752440f));
                v01 = 0.5f * v01 * (1.0f + erff(v01 * 0.70710678118654752440f));
                v10 = 0.5f * v10 * (1.0f + erff(v10 * 0.70710678118654752440f));
                v11 = 0.5f * v11 * (1.0f + erff(v11 * 0.70710678118654752440f));
            }
            float2 o0 = {v00, v01};
            float2 o1 = {v10, v11};
            *(float2*)(C + (size_t)r1 * ldC + ocol0 + cl) = o0;
            *(float2*)(C + (size_t)(r1 + 8) * ldC + ocol0 + cl) = o1;
        }
    }
}

// ---------------- fused causal flash attention (TF32 tensor cores) ----------------
// BM=128 queries/CTA, BN=64 keys/step, HD=64. 8 warps; warp w owns query rows
// [w*16, w*16+16). grid: (T/128, B*H). QKV strided in fused buffer (ld=QKVLD).
#define FBM 128
#define FBN 64
#define QP 68
#define KP 68
#define VP 72
#define PP 68
#define FLASH_SMEM ((FBM*QP + FBN*KP + FBN*VP + FBM*PP) * 4)

__global__ __launch_bounds__(256) void flash_attn_kernel(
        const float* __restrict__ QKV, float* __restrict__ O) {
    extern __shared__ float sm[];
    float* Qs = sm;                       // [128][QP]  tf32
    float* Ks = Qs + FBM * QP;            // [64][KP]   tf32
    float* Vs = Ks + FBN * KP;            // [64][VP]   tf32
    float* Ps = Vs + FBN * VP;            // [128][PP]  tf32 (warp-private rows)

    const int tx = threadIdx.x;
    const int warp = tx >> 5;
    const int lane = tx & 31;
    const int g  = lane >> 2;
    const int tg = lane & 3;
    const int qb = gridDim.x - 1 - blockIdx.x;   // long CTAs first
    const int bh = blockIdx.y;
    const int bb = bh >> 4, hh = bh & 15;
    const int qbase = qb * FBM;

    const float* qptr = QKV + (size_t)bb * TT * QKVLD + hh * HD;
    const float* kptr = qptr + 1024;
    const float* vptr = qptr + 2048;

    // load Q tile (stays resident)
    #pragma unroll
    for (int i = 0; i < 8; i++) {
        int idx = tx + i * 256;
        int r = idx >> 4, c = (idx & 15) * 4;
        float4 v = *(const float4*)(qptr + (size_t)(qbase + r) * QKVLD + c);
        float* d = &Qs[r * QP + c];
        d[0] = tf32r(v.x); d[1] = tf32r(v.y); d[2] = tf32r(v.z); d[3] = tf32r(v.w);
    }

    float m0 = -1e30f, m1 = -1e30f, l0 = 0.f, l1 = 0.f;
    float o[8][4];
    #pragma unroll
    for (int nt = 0; nt < 8; nt++)
        #pragma unroll
        for (int c = 0; c < 4; c++) o[nt][c] = 0.f;

    const int myrow0 = qbase + warp * 16;
    const float sl2e = 0.125f * 1.44269504088896f;   // scale * log2(e)

    const int kbmax = 2 * qb + 1;
    for (int kb = 0; kb <= kbmax; kb++) {
        __syncthreads();     // prev PV reads of Vs done
        // load K,V tiles for this key block
        #pragma unroll
        for (int i = 0; i < 4; i++) {
            int idx = tx + i * 256;
            int r = idx >> 4, c = (idx & 15) * 4;
            size_t gro = (size_t)(kb * FBN + r) * QKVLD + c;
            float4 kv = *(const float4*)(kptr + gro);
            float* dk = &Ks[r * KP + c];
            dk[0] = tf32r(kv.x); dk[1] = tf32r(kv.y); dk[2] = tf32r(kv.z); dk[3] = tf32r(kv.w);
            float4 vv = *(const float4*)(vptr + gro);
            float* dv = &Vs[r * VP + c];
            dv[0] = tf32r(vv.x); dv[1] = tf32r(vv.y); dv[2] = tf32r(vv.z); dv[3] = tf32r(vv.w);
        }
        __syncthreads();

        if (kb * FBN > myrow0 + 15) continue;   // warp fully masked (sync counts still match)

        // S = Q @ K^T   (warp: 16 rows x 64 keys)
        float s[8][4];
        #pragma unroll
        for (int nt = 0; nt < 8; nt++)
            #pragma unroll
            for (int c = 0; c < 4; c++) s[nt][c] = 0.f;

        #pragma unroll
        for (int kc = 0; kc < 64; kc += 8) {
            uint32_t a[4];
            const float* q0 = &Qs[(warp * 16 + g) * QP + kc + tg];
            a[0] = __float_as_uint(q0[0]);
            a[1] = __float_as_uint(q0[8 * QP]);
            a[2] = __float_as_uint(q0[4]);
            a[3] = __float_as_uint(q0[8 * QP + 4]);
            #pragma unroll
            for (int nt = 0; nt < 8; nt++) {
                uint32_t b[2];
                const float* kk = &Ks[(nt * 8 + g) * KP + kc + tg];
                b[0] = __float_as_uint(kk[0]);
                b[1] = __float_as_uint(kk[4]);
                mma_tf32(s[nt], a, b);
            }
        }

        // scale + causal mask
        const int r0 = myrow0 + g, r1 = r0 + 8;
        const bool dm = (kb >= 2 * qb);
        #pragma unroll
        for (int nt = 0; nt < 8; nt++) {
            int c0 = kb * FBN + nt * 8 + 2 * tg;
            s[nt][0] *= sl2e; s[nt][1] *= sl2e;
            s[nt][2] *= sl2e; s[nt][3] *= sl2e;
            if (dm) {
                if (c0     > r0) s[nt][0] = -1e30f;
                if (c0 + 1 > r0) s[nt][1] = -1e30f;
                if (c0     > r1) s[nt][2] = -1e30f;
                if (c0 + 1 > r1) s[nt][3] = -1e30f;
            }
        }

        // row max (2 rows/thread), reduce over 4 lanes sharing a row
        float rm0 = -1e30f, rm1 = -1e30f;
        #pragma unroll
        for (int nt = 0; nt < 8; nt++) {
            rm0 = fmaxf(rm0, fmaxf(s[nt][0], s[nt][1]));
            rm1 = fmaxf(rm1, fmaxf(s[nt][2], s[nt][3]));
        }
        rm0 = fmaxf(rm0, __shfl_xor_sync(0xffffffffu, rm0, 1));
        rm0 = fmaxf(rm0, __shfl_xor_sync(0xffffffffu, rm0, 2));
        rm1 = fmaxf(rm1, __shfl_xor_sync(0xffffffffu, rm1, 1));
        rm1 = fmaxf(rm1, __shfl_xor_sync(0xffffffffu, rm1, 2));
        float mn0 = fmaxf(m0, rm0), mn1 = fmaxf(m1, rm1);
        float al0 = exp2a(m0 - mn0), al1 = exp2a(m1 - mn1);
        m0 = mn0; m1 = mn1;

        __syncwarp();
        float rs0 = 0.f, rs1 = 0.f;
        #pragma unroll
        for (int nt = 0; nt < 8; nt++) {
            float p0 = tf32r(exp2a(s[nt][0] - m0));
            float p1 = tf32r(exp2a(s[nt][1] - m0));
            float p2 = tf32r(exp2a(s[nt][2] - m1));
            float p3 = tf32r(exp2a(s[nt][3] - m1));
            rs0 += p0 + p1;
            rs1 += p2 + p3;
            float* pp = &Ps[(warp * 16 + g) * PP + nt * 8 + 2 * tg];
            float2 w0 = {p0, p1};
            float2 w1 = {p2, p3};
            *(float2*)pp = w0;
            *(float2*)(pp + 8 * PP) = w1;
        }
        rs0 += __shfl_xor_sync(0xffffffffu, rs0, 1);
        rs0 += __shfl_xor_sync(0xffffffffu, rs0, 2);
        rs1 += __shfl_xor_sync(0xffffffffu, rs1, 1);
        rs1 += __shfl_xor_sync(0xffffffffu, rs1, 2);
        l0 = l0 * al0 + rs0;
        l1 = l1 * al1 + rs1;
        #pragma unroll
        for (int nt = 0; nt < 8; nt++) {
            o[nt][0] *= al0; o[nt][1] *= al0;
            o[nt][2] *= al1; o[nt][3] *= al1;
        }
        __syncwarp();

        // O += P @ V   (warp-private P rows)
        #pragma unroll
        for (int kc = 0; kc < 8; kc++) {
            uint32_t a[4];
            const float* pr = &Ps[(warp * 16 + g) * PP + kc * 8 + tg];
            a[0] = __float_as_uint(pr[0]);
            a[1] = __float_as_uint(pr[8 * PP]);
            a[2] = __float_as_uint(pr[4]);
            a[3] = __float_as_uint(pr[8 * PP + 4]);
            #pragma unroll
            for (int nt = 0; nt < 8; nt++) {
                uint32_t b[2];
                const float* vr = &Vs[(kc * 8 + tg) * VP + nt * 8 + g];
                b[0] = __float_as_uint(vr[0]);
                b[1] = __float_as_uint(vr[4 * VP]);
                mma_tf32(o[nt], a, b);
            }
        }
    }

    // normalize + store (y layout [B,T,H*HD])
    float i0 = 1.0f / l0, i1 = 1.0f / l1;
    float* ob = O + ((size_t)bb * TT + myrow0 + g) * DD + hh * HD;
    #pragma unroll
    for (int nt = 0; nt < 8; nt++) {
        int c = nt * 8 + 2 * tg;
        float2 v0 = {o[nt][0] * i0, o[nt][1] * i0};
        float2 v1 = {o[nt][2] * i1, o[nt][3] * i1};
        *(float2*)(ob + c) = v0;
        *(float2*)(ob + (size_t)8 * DD + c) = v1;
    }
}

// ---------------- host orchestration ----------------
static float* sym(const void* s) {
    void* p = nullptr;
    cudaGetSymbolAddress(&p, s);
    return (float*)p;
}

extern "C" void kernel_launch(void* const* d_in, const int* in_sizes, int n_in,
                              void* d_out, int out_size) {
    const float* seq  = (const float*)d_in[0];
    const float* Wq   = (const float*)d_in[1];
    const float* bq   = (const float*)d_in[2];
    const float* Wk   = (const float*)d_in[3];
    const float* bk   = (const float*)d_in[4];
    const float* Wv   = (const float*)d_in[5];
    const float* bv   = (const float*)d_in[6];
    const float* Wo   = (const float*)d_in[7];
    const float* bo   = (const float*)d_in[8];
    const float* Wz   = (const float*)d_in[9];
    const float* bz   = (const float*)d_in[10];
    const float* Wr   = (const float*)d_in[11];
    const float* br   = (const float*)d_in[12];
    const float* W1   = (const float*)d_in[13];
    const float* b1   = (const float*)d_in[14];
    const float* W2   = (const float*)d_in[15];
    const float* b2   = (const float*)d_in[16];
    const float* ln1w = (const float*)d_in[17];
    const float* ln1b = (const float*)d_in[18];
    const float* ln2w = (const float*)d_in[19];
    const float* ln2b = (const float*)d_in[20];
    const float* lnfw = (const float*)d_in[21];
    const float* lnfb = (const float*)d_in[22];

    float* x     = sym(g_x);
    float* xn    = sym(g_xn);
    float* qkvzr = sym(g_qkvzr);
    float* y     = sym(g_y);
    float* xat   = sym(g_xat);
    float* zs    = sym(g_zs);
    float* mlp   = sym(g_mlp);
    float* h1    = sym(g_h1);

    static bool attr_done = false;
    if (!attr_done) {
        cudaFuncSetAttribute(flash_attn_kernel,
                             cudaFuncAttributeMaxDynamicSharedMemorySize, FLASH_SMEM);
        attr_done = true;
    }

    const int nElem = NTOK * DD;
    const int ethreads = 256;
    const int eblocks = (nElem + ethreads - 1) / ethreads;

    copy_kernel<<<eblocks, ethreads>>>(x, seq, nElem);

    dim3 gQKVZR(40, 32);
    dim3 gD(8, 32);
    dim3 gF(32, 32);
    dim3 gFA(TT / FBM, BB * HH);   // (16, 32)

    for (int l = 0; l < NL; l++) {
        GemmArgs a5, a1, aw1, aw2;
        a5.w[0] = Wq + (size_t)l * DD * DD;  a5.bias[0] = bq + l * DD;
        a5.w[1] = Wk + (size_t)l * DD * DD;  a5.bias[1] = bk + l * DD;
        a5.w[2] = Wv + (size_t)l * DD * DD;  a5.bias[2] = bv + l * DD;
        a5.w[3] = Wz + (size_t)l * DD * DD;  a5.bias[3] = bz + l * DD;
        a5.w[4] = Wr + (size_t)l * DD * DD;  a5.bias[4] = br + l * DD;
        a1.w[0] = Wo + (size_t)l * DD * DD;  a1.bias[0] = bo + l * DD;
        for (int j = 1; j < 5; j++) { a1.w[j] = a1.w[0]; a1.bias[j] = a1.bias[0]; }
        aw1.w[0] = W1 + (size_t)l * DD * DF; aw1.bias[0] = b1 + l * DF;
        for (int j = 1; j < 5; j++) { aw1.w[j] = aw1.w[0]; aw1.bias[j] = aw1.bias[0]; }
        aw2.w[0] = W2 + (size_t)l * DF * DD; aw2.bias[0] = b2 + l * DD;
        for (int j = 1; j < 5; j++) { aw2.w[j] = aw2.w[0]; aw2.bias[j] = aw2.bias[0]; }

        layernorm_kernel<<<NTOK, 256>>>(x, ln1w + l * DD, ln1b + l * DD, xn);

        // fused Q,K,V,Z,R projections -> qkvzr [NTOK, 5120]
        gemm_tf32_kernel<<<gQKVZR, 256>>>(xn, a5, qkvzr, DD, 8, DD, QKVLD, 0);

        // fused causal attention
        flash_attn_kernel<<<gFA, 256, FLASH_SMEM>>>(qkvzr, y);

        gemm_tf32_kernel<<<gD, 256>>>(y, a1, xat, DD, 8, DD, DD, 0);
        gate1_kernel<<<eblocks, ethreads>>>(x, xat, qkvzr, zs, nElem);

        layernorm_kernel<<<NTOK, 256>>>(x, ln2w + l * DD, ln2b + l * DD, xn);
        gemm_tf32_kernel<<<gF, 256>>>(xn, aw1, h1, DD, 32, DF, DF, 1);   // +GELU
        gemm_tf32_kernel<<<gD, 256>>>(h1, aw2, mlp, DF, 8, DD, DD, 0);
        gate2_kernel<<<eblocks, ethreads>>>(x, mlp, zs, seq, nElem);
    }

    layernorm_kernel<<<NTOK, 256>>>(x, lnfw, lnfb, (float*)d_out);
}

// round 5
// speedup vs baseline: 6.0259x; 1.9566x over previous
#include <cuda_runtime.h>
#include <cuda_fp16.h>
#include <math.h>
#include <stdint.h>

// ---------------- problem constants ----------------
#define BB 2
#define TT 2048
#define DD 1024
#define HH 16
#define HD 64
#define NL 6
#define DF 4096
#define NTOK (BB*TT)          // 4096 rows
#define QKVLD 5120            // fused QKVZR row stride
#define EPSLN 1e-5f

// ---------------- device scratch (no allocs allowed) ----------------
__device__ float  g_x   [NTOK*DD];
__device__ __half g_xn  [NTOK*DD];
__device__ __half g_qkvzr[(size_t)NTOK*QKVLD];
__device__ __half g_y   [NTOK*DD];
__device__ float  g_xat [NTOK*DD];
__device__ float  g_zs  [NTOK*DD];
__device__ float  g_mlp [NTOK*DD];
__device__ __half g_h1  [(size_t)NTOK*DF];

// transposed fp16 weights, K-major [N][K]
__device__ __half g_wtqkvzr[(size_t)NL*QKVLD*DD];
__device__ __half g_wto    [(size_t)NL*DD*DD];
__device__ __half g_wt1    [(size_t)NL*DF*DD];
__device__ __half g_wt2    [(size_t)NL*DD*DF];
__device__ float  g_bcat   [NL*QKVLD];

// ---------------- helpers ----------------
__device__ __forceinline__ float exp2a(float x) {
    float y;
    asm("ex2.approx.f32 %0, %1;" : "=f"(y) : "f"(x));
    return y;
}

__device__ __forceinline__ void mma_f16(float* d, const uint32_t* a, const uint32_t* b) {
    asm volatile(
        "mma.sync.aligned.m16n8k16.row.col.f32.f16.f16.f32 "
        "{%0,%1,%2,%3}, {%4,%5,%6,%7}, {%8,%9}, {%0,%1,%2,%3};"
        : "+f"(d[0]), "+f"(d[1]), "+f"(d[2]), "+f"(d[3])
        : "r"(a[0]), "r"(a[1]), "r"(a[2]), "r"(a[3]),
          "r"(b[0]), "r"(b[1]));
}

__device__ __forceinline__ float sigmoidf_(float x) { return 1.0f / (1.0f + expf(-x)); }

__device__ __forceinline__ uint32_t smem_u32(const void* p) {
    uint32_t a;
    asm("{ .reg .u64 t; cvta.to.shared.u64 t, %1; cvt.u32.u64 %0, t; }" : "=r"(a) : "l"(p));
    return a;
}

__device__ __forceinline__ void cp16(uint32_t dst, const void* src) {
    asm volatile("cp.async.cg.shared.global [%0], [%1], 16;" :: "r"(dst), "l"(src) : "memory");
}
#define CP_COMMIT() asm volatile("cp.async.commit_group;" ::: "memory")
#define CP_WAIT(n)  asm volatile("cp.async.wait_group %0;" :: "n"(n) : "memory")

// ---------------- small elementwise kernels ----------------
__global__ void copy_kernel(float* __restrict__ dst, const float* __restrict__ src, int n) {
    int i = blockIdx.x * blockDim.x + threadIdx.x;
    if (i < n) dst[i] = src[i];
}

__global__ void gate1_kernel(float* __restrict__ x, const float* __restrict__ xat,
                             const __half* __restrict__ qkvzr, float* __restrict__ zs, int n) {
    int i = blockIdx.x * blockDim.x + threadIdx.x;
    if (i >= n) return;
    int row = i >> 10;
    int col = i & 1023;
    size_t base = (size_t)row * QKVLD + col;
    float z = sigmoidf_(__half2float(qkvzr[base + 3072]));
    float r = sigmoidf_(__half2float(qkvzr[base + 4096]));
    float h = tanhf(r * xat[i]);
    x[i] = (1.0f - z) * x[i] + z * h;
    zs[i] = z;
}

__global__ void gate2_kernel(float* __restrict__ x, const float* __restrict__ mlp,
                             const float* __restrict__ zs, const float* __restrict__ src, int n) {
    int i = blockIdx.x * blockDim.x + threadIdx.x;
    if (i >= n) return;
    float z = zs[i];
    x[i] = (1.0f - z) * x[i] + z * mlp[i] + src[i];
}

// ---------------- layernorm (fp16 out / fp32 out) ----------------
template <typename OutT>
__global__ __launch_bounds__(256) void layernorm_kernel(
        const float* __restrict__ x, const float* __restrict__ w,
        const float* __restrict__ b, OutT* __restrict__ out) {
    int row = blockIdx.x;
    const float* xr = x + (size_t)row * DD;
    OutT* orow = out + (size_t)row * DD;
    int tid = threadIdx.x;
    __shared__ float s1[256], s2[256];
    float sum = 0.f, ss = 0.f;
    #pragma unroll
    for (int j = tid; j < DD; j += 256) { float v = xr[j]; sum += v; ss += v * v; }
    s1[tid] = sum; s2[tid] = ss;
    __syncthreads();
    for (int s = 128; s > 0; s >>= 1) {
        if (tid < s) { s1[tid] += s1[tid + s]; s2[tid] += s2[tid + s]; }
        __syncthreads();
    }
    float mu = s1[0] * (1.0f / DD);
    float var = s2[0] * (1.0f / DD) - mu * mu;
    float rs = rsqrtf(var + EPSLN);
    for (int j = tid; j < DD; j += 256)
        orow[j] = (OutT)((xr[j] - mu) * rs * w[j] + b[j]);
}

// ---------------- weight transpose to fp16: dst[N][K] = (half)src[K][N] ----------------
__global__ __launch_bounds__(256) void transpose_h_kernel(
        const float* __restrict__ src, __half* __restrict__ dst, int K, int N) {
    __shared__ float tile[32][33];
    int k0 = blockIdx.y * 32, n0 = blockIdx.x * 32;
    int tx = threadIdx.x & 31, ty = threadIdx.x >> 5;
    #pragma unroll
    for (int i = 0; i < 4; i++)
        tile[ty + i * 8][tx] = src[(size_t)(k0 + ty + i * 8) * N + n0 + tx];
    __syncthreads();
    #pragma unroll
    for (int i = 0; i < 4; i++)
        dst[(size_t)(n0 + ty + i * 8) * K + k0 + tx] = __float2half(tile[tx][ty + i * 8]);
}

__global__ void biaspack_kernel(const float* __restrict__ bq, const float* __restrict__ bk,
                                const float* __restrict__ bv, const float* __restrict__ bz,
                                const float* __restrict__ br, float* __restrict__ out) {
    int i = blockIdx.x * blockDim.x + threadIdx.x;
    if (i >= NL * QKVLD) return;
    int l = i / QKVLD, j = i % QKVLD;
    int m = j >> 10, c = j & 1023;
    const float* src = (m == 0) ? bq : (m == 1) ? bk : (m == 2) ? bv : (m == 3) ? bz : br;
    out[i] = src[l * 1024 + c];
}

// ---------------- fp16 tensor-core GEMM ----------------
// C[M,N] = A[M,K](fp16, lda=K) @ WT[N,K]^T(fp16) + bias. BM=BN=128, BK=64.
// 256 threads, 8 warps 2x4, warp tile 64x32. cp.async 2-stage pipeline.
#define GBM 128
#define GBN 128
#define GBK 64
#define GP 72   // smem pitch in halves
#define GTILE (GBM*GP)
#define GEMM_SMEM (4*GTILE*2)   // A[2] + B[2], halves

__global__ __launch_bounds__(256) void gemm_f16_kernel(
        const __half* __restrict__ A, const __half* __restrict__ WT,
        const float* __restrict__ bias, void* __restrict__ Cout,
        int K, int ldC, int epi, int outHalf) {
    extern __shared__ char dynsm[];
    __half* As = (__half*)dynsm;
    __half* Bs = As + 2 * GTILE;

    const int tid  = threadIdx.x;
    const int warp = tid >> 5;
    const int lane = tid & 31;
    const int g    = lane >> 2;
    const int tg   = lane & 3;
    const int row0 = blockIdx.y * GBM;
    const int col0 = blockIdx.x * GBN;
    const int wm   = (warp >> 2) * 64;
    const int wn   = (warp & 3) * 32;

    const int fr = tid >> 3;          // 0..31
    const int fc = (tid & 7) * 8;     // 0..56

    float acc[4][4][4];
    #pragma unroll
    for (int i = 0; i < 4; i++)
        #pragma unroll
        for (int j = 0; j < 4; j++)
            #pragma unroll
            for (int c = 0; c < 4; c++) acc[i][j][c] = 0.f;

    const __half* Ag = A  + (size_t)row0 * K;
    const __half* Bg = WT + (size_t)col0 * K;
    const uint32_t as_base = smem_u32(As);
    const uint32_t bs_base = smem_u32(Bs);

    auto issue = [&](int it, int buf) {
        const int k0 = it * GBK;
        uint32_t ad = as_base + (buf * GTILE) * 2;
        uint32_t bd = bs_base + (buf * GTILE) * 2;
        #pragma unroll
        for (int i = 0; i < 4; i++) {
            int r = fr + i * 32;
            cp16(ad + (r * GP + fc) * 2, Ag + (size_t)r * K + k0 + fc);
            cp16(bd + (r * GP + fc) * 2, Bg + (size_t)r * K + k0 + fc);
        }
    };

    issue(0, 0);
    CP_COMMIT();

    const int nit = K / GBK;
    for (int it = 0; it < nit; it++) {
        const int buf = it & 1;
        if (it + 1 < nit) { issue(it + 1, buf ^ 1); CP_COMMIT(); CP_WAIT(1); }
        else              { CP_WAIT(0); }
        __syncthreads();

        const __half* Ab = As + buf * GTILE;
        const __half* Bb = Bs + buf * GTILE;
        #pragma unroll
        for (int ks = 0; ks < 4; ks++) {
            const int kc = ks * 16;
            uint32_t af[4][4], bf[4][2];
            #pragma unroll
            for (int fm = 0; fm < 4; fm++) {
                const __half* p = Ab + (wm + fm * 16 + g) * GP + kc + 2 * tg;
                af[fm][0] = *(const uint32_t*)p;
                af[fm][1] = *(const uint32_t*)(p + 8 * GP);
                af[fm][2] = *(const uint32_t*)(p + 8);
                af[fm][3] = *(const uint32_t*)(p + 8 * GP + 8);
            }
            #pragma unroll
            for (int fn = 0; fn < 4; fn++) {
                const __half* q = Bb + (wn + fn * 8 + g) * GP + kc + 2 * tg;
                bf[fn][0] = *(const uint32_t*)q;
                bf[fn][1] = *(const uint32_t*)(q + 8);
            }
            #pragma unroll
            for (int fm = 0; fm < 4; fm++)
                #pragma unroll
                for (int fn = 0; fn < 4; fn++)
                    mma_f16(acc[fm][fn], af[fm], bf[fn]);
        }
        __syncthreads();
    }

    // epilogue
    #pragma unroll
    for (int fm = 0; fm < 4; fm++) {
        int r1 = row0 + wm + fm * 16 + g;
        #pragma unroll
        for (int fn = 0; fn < 4; fn++) {
            int cl = wn + fn * 8 + tg * 2;
            float bz0 = bias[col0 + cl];
            float bz1 = bias[col0 + cl + 1];
            float v00 = acc[fm][fn][0] + bz0;
            float v01 = acc[fm][fn][1] + bz1;
            float v10 = acc[fm][fn][2] + bz0;
            float v11 = acc[fm][fn][3] + bz1;
            if (epi == 1) {
                v00 = 0.5f * v00 * (1.0f + erff(v00 * 0.70710678118654752440f));
                v01 = 0.5f * v01 * (1.0f + erff(v01 * 0.70710678118654752440f));
                v10 = 0.5f * v10 * (1.0f + erff(v10 * 0.70710678118654752440f));
                v11 = 0.5f * v11 * (1.0f + erff(v11 * 0.70710678118654752440f));
            }
            if (outHalf) {
                __half* ch = (__half*)Cout;
                *(__half2*)(ch + (size_t)r1 * ldC + col0 + cl) = __floats2half2_rn(v00, v01);
                *(__half2*)(ch + (size_t)(r1 + 8) * ldC + col0 + cl) = __floats2half2_rn(v10, v11);
            } else {
                float* cf = (float*)Cout;
                float2 o0 = {v00, v01};
                float2 o1 = {v10, v11};
                *(float2*)(cf + (size_t)r1 * ldC + col0 + cl) = o0;
                *(float2*)(cf + (size_t)(r1 + 8) * ldC + col0 + cl) = o1;
            }
        }
    }
}

// ---------------- fused causal flash attention (fp16 MMA) ----------------
// BM=128 q/CTA, BN=64 keys/step. 8 warps; warp w owns q rows [w*16, w*16+16).
#define FBM 128
#define FBN 64
#define FP 72   // pitch in halves
#define FLASH_SMEM ((FBM*FP + FBN*FP + FBN*FP + FBM*FP) * 2)

__global__ __launch_bounds__(256) void flash_attn_kernel(
        const __half* __restrict__ QKV, __half* __restrict__ O) {
    extern __shared__ char dynsm[];
    __half* Qs = (__half*)dynsm;          // [128][FP]
    __half* Ks = Qs + FBM * FP;           // [64][FP]
    __half* Vt = Ks + FBN * FP;           // [64 d][FP tokens], swizzled
    __half* Ps = Vt + FBN * FP;           // [128][FP]

    const int tx = threadIdx.x;
    const int warp = tx >> 5;
    const int lane = tx & 31;
    const int g  = lane >> 2;
    const int tg = lane & 3;
    const int qb = gridDim.x - 1 - blockIdx.x;
    const int bh = blockIdx.y;
    const int bb = bh >> 4, hh = bh & 15;
    const int qbase = qb * FBM;

    const __half* qptr = QKV + (size_t)bb * TT * QKVLD + hh * HD;
    const __half* kptr = qptr + 1024;
    const __half* vptr = qptr + 2048;

    // load Q (resident)
    #pragma unroll
    for (int i = 0; i < 4; i++) {
        int idx = tx + i * 256;
        int r = idx >> 3, c8 = (idx & 7) * 8;
        *(uint4*)&Qs[r * FP + c8] =
            *(const uint4*)(qptr + (size_t)(qbase + r) * QKVLD + c8);
    }

    float m0 = -1e30f, m1 = -1e30f, l0 = 0.f, l1 = 0.f;
    float o[8][4];
    #pragma unroll
    for (int nt = 0; nt < 8; nt++)
        #pragma unroll
        for (int c = 0; c < 4; c++) o[nt][c] = 0.f;

    const int myrow0 = qbase + warp * 16;
    const float sl2e = 0.125f * 1.44269504088896f;

    const int kbmax = 2 * qb + 1;
    for (int kb = 0; kb <= kbmax; kb++) {
        __syncthreads();
        // K tile [key][d]
        #pragma unroll
        for (int i = 0; i < 2; i++) {
            int idx = tx + i * 256;
            int r = idx >> 3, c8 = (idx & 7) * 8;
            *(uint4*)&Ks[r * FP + c8] =
                *(const uint4*)(kptr + (size_t)(kb * FBN + r) * QKVLD + c8);
        }
        // V^T tile [d][token], token swizzled by 2*(d>>3 & 7)
        #pragma unroll
        for (int i = 0; i < 2; i++) {
            int idx = tx + i * 256;
            int token = idx >> 3, d8 = (idx & 7) * 8;
            uint4 raw = *(const uint4*)(vptr + (size_t)(kb * FBN + token) * QKVLD + d8);
            const __half* hv = (const __half*)&raw;
            int tsw = token ^ (2 * (idx & 7));
            #pragma unroll
            for (int j = 0; j < 8; j++)
                Vt[(d8 + j) * FP + tsw] = hv[j];
        }
        __syncthreads();

        if (kb * FBN > myrow0 + 15) continue;

        // S = Q @ K^T  (16 x 64)
        float s[8][4];
        #pragma unroll
        for (int nt = 0; nt < 8; nt++)
            #pragma unroll
            for (int c = 0; c < 4; c++) s[nt][c] = 0.f;

        #pragma unroll
        for (int ks = 0; ks < 4; ks++) {
            const int kc = ks * 16;
            uint32_t a[4];
            const __half* p = &Qs[(warp * 16 + g) * FP + kc + 2 * tg];
            a[0] = *(const uint32_t*)p;
            a[1] = *(const uint32_t*)(p + 8 * FP);
            a[2] = *(const uint32_t*)(p + 8);
            a[3] = *(const uint32_t*)(p + 8 * FP + 8);
            #pragma unroll
            for (int nt = 0; nt < 8; nt++) {
                uint32_t b[2];
                const __half* q = &Ks[(nt * 8 + g) * FP + kc + 2 * tg];
                b[0] = *(const uint32_t*)q;
                b[1] = *(const uint32_t*)(q + 8);
                mma_f16(s[nt], a, b);
            }
        }

        // scale + causal mask
        const int r0 = myrow0 + g, r1 = r0 + 8;
        const bool dm = (kb >= 2 * qb);
        #pragma unroll
        for (int nt = 0; nt < 8; nt++) {
            int c0 = kb * FBN + nt * 8 + 2 * tg;
            s[nt][0] *= sl2e; s[nt][1] *= sl2e;
            s[nt][2] *= sl2e; s[nt][3] *= sl2e;
            if (dm) {
                if (c0     > r0) s[nt][0] = -1e30f;
                if (c0 + 1 > r0) s[nt][1] = -1e30f;
                if (c0     > r1) s[nt][2] = -1e30f;
                if (c0 + 1 > r1) s[nt][3] = -1e30f;
            }
        }

        // online softmax
        float rm0 = -1e30f, rm1 = -1e30f;
        #pragma unroll
        for (int nt = 0; nt < 8; nt++) {
            rm0 = fmaxf(rm0, fmaxf(s[nt][0], s[nt][1]));
            rm1 = fmaxf(rm1, fmaxf(s[nt][2], s[nt][3]));
        }
        rm0 = fmaxf(rm0, __shfl_xor_sync(0xffffffffu, rm0, 1));
        rm0 = fmaxf(rm0, __shfl_xor_sync(0xffffffffu, rm0, 2));
        rm1 = fmaxf(rm1, __shfl_xor_sync(0xffffffffu, rm1, 1));
        rm1 = fmaxf(rm1, __shfl_xor_sync(0xffffffffu, rm1, 2));
        float mn0 = fmaxf(m0, rm0), mn1 = fmaxf(m1, rm1);
        float al0 = exp2a(m0 - mn0), al1 = exp2a(m1 - mn1);
        m0 = mn0; m1 = mn1;

        __syncwarp();
        float rs0 = 0.f, rs1 = 0.f;
        #pragma unroll
        for (int nt = 0; nt < 8; nt++) {
            float p0 = exp2a(s[nt][0] - m0);
            float p1 = exp2a(s[nt][1] - m0);
            float p2 = exp2a(s[nt][2] - m1);
            float p3 = exp2a(s[nt][3] - m1);
            rs0 += p0 + p1;
            rs1 += p2 + p3;
            __half* pp = &Ps[(warp * 16 + g) * FP + nt * 8 + 2 * tg];
            *(__half2*)pp = __floats2half2_rn(p0, p1);
            *(__half2*)(pp + 8 * FP) = __floats2half2_rn(p2, p3);
        }
        rs0 += __shfl_xor_sync(0xffffffffu, rs0, 1);
        rs0 += __shfl_xor_sync(0xffffffffu, rs0, 2);
        rs1 += __shfl_xor_sync(0xffffffffu, rs1, 1);
        rs1 += __shfl_xor_sync(0xffffffffu, rs1, 2);
        l0 = l0 * al0 + rs0;
        l1 = l1 * al1 + rs1;
        #pragma unroll
        for (int nt = 0; nt < 8; nt++) {
            o[nt][0] *= al0; o[nt][1] *= al0;
            o[nt][2] *= al1; o[nt][3] *= al1;
        }
        __syncwarp();

        // O += P @ V  (A = P rows, B = V^T with swizzle)
        #pragma unroll
        for (int ks = 0; ks < 4; ks++) {
            const int kc = ks * 16;
            uint32_t a[4];
            const __half* p = &Ps[(warp * 16 + g) * FP + kc + 2 * tg];
            a[0] = *(const uint32_t*)p;
            a[1] = *(const uint32_t*)(p + 8 * FP);
            a[2] = *(const uint32_t*)(p + 8);
            a[3] = *(const uint32_t*)(p + 8 * FP + 8);
            #pragma unroll
            for (int nt = 0; nt < 8; nt++) {
                uint32_t b[2];
                const int d = nt * 8 + g;
                const int sw = 2 * (nt & 7);
                b[0] = *(const uint32_t*)&Vt[d * FP + ((kc + 2 * tg) ^ sw)];
                b[1] = *(const uint32_t*)&Vt[d * FP + ((kc + 2 * tg + 8) ^ sw)];
                mma_f16(o[nt], a, b);
            }
        }
    }

    // normalize + store fp16 y [B,T,H*HD]
    float i0 = 1.0f / l0, i1 = 1.0f / l1;
    __half* ob = O + ((size_t)bb * TT + myrow0 + g) * DD + hh * HD;
    #pragma unroll
    for (int nt = 0; nt < 8; nt++) {
        int c = nt * 8 + 2 * tg;
        *(__half2*)(ob + c) = __floats2half2_rn(o[nt][0] * i0, o[nt][1] * i0);
        *(__half2*)(ob + (size_t)8 * DD + c) = __floats2half2_rn(o[nt][2] * i1, o[nt][3] * i1);
    }
}

// ---------------- host orchestration ----------------
static void* symv(const void* s) {
    void* p = nullptr;
    cudaGetSymbolAddress(&p, s);
    return p;
}

extern "C" void kernel_launch(void* const* d_in, const int* in_sizes, int n_in,
                              void* d_out, int out_size) {
    const float* seq  = (const float*)d_in[0];
    const float* Wq   = (const float*)d_in[1];
    const float* bq   = (const float*)d_in[2];
    const float* Wk   = (const float*)d_in[3];
    const float* bk   = (const float*)d_in[4];
    const float* Wv   = (const float*)d_in[5];
    const float* bv   = (const float*)d_in[6];
    const float* Wo   = (const float*)d_in[7];
    const float* bo   = (const float*)d_in[8];
    const float* Wz   = (const float*)d_in[9];
    const float* bz   = (const float*)d_in[10];
    const float* Wr   = (const float*)d_in[11];
    const float* br   = (const float*)d_in[12];
    const float* W1   = (const float*)d_in[13];
    const float* b1   = (const float*)d_in[14];
    const float* W2   = (const float*)d_in[15];
    const float* b2   = (const float*)d_in[16];
    const float* ln1w = (const float*)d_in[17];
    const float* ln1b = (const float*)d_in[18];
    const float* ln2w = (const float*)d_in[19];
    const float* ln2b = (const float*)d_in[20];
    const float* lnfw = (const float*)d_in[21];
    const float* lnfb = (const float*)d_in[22];

    float*  x     = (float*)symv(g_x);
    __half* xn    = (__half*)symv(g_xn);
    __half* qkvzr = (__half*)symv(g_qkvzr);
    __half* y     = (__half*)symv(g_y);
    float*  xat   = (float*)symv(g_xat);
    float*  zs    = (float*)symv(g_zs);
    float*  mlp   = (float*)symv(g_mlp);
    __half* h1    = (__half*)symv(g_h1);
    __half* wtqkv = (__half*)symv(g_wtqkvzr);
    __half* wto   = (__half*)symv(g_wto);
    __half* wt1   = (__half*)symv(g_wt1);
    __half* wt2   = (__half*)symv(g_wt2);
    float*  bcat  = (float*)symv(g_bcat);

    static bool attr_done = false;
    if (!attr_done) {
        cudaFuncSetAttribute(flash_attn_kernel,
                             cudaFuncAttributeMaxDynamicSharedMemorySize, FLASH_SMEM);
        cudaFuncSetAttribute(gemm_f16_kernel,
                             cudaFuncAttributeMaxDynamicSharedMemorySize, GEMM_SMEM);
        attr_done = true;
    }

    const int nElem = NTOK * DD;
    const int ethreads = 256;
    const int eblocks = (nElem + ethreads - 1) / ethreads;

    // ---- weight pre-transpose to fp16 + bias packing ----
    dim3 tD(DD / 32, DD / 32);
    dim3 t1(DF / 32, DD / 32);
    dim3 t2(DD / 32, DF / 32);
    for (int l = 0; l < NL; l++) {
        size_t o5 = (size_t)l * QKVLD * DD;
        transpose_h_kernel<<<tD, 256>>>(Wq + (size_t)l * DD * DD, wtqkv + o5 + 0ull * DD * DD, DD, DD);
        transpose_h_kernel<<<tD, 256>>>(Wk + (size_t)l * DD * DD, wtqkv + o5 + 1ull * DD * DD, DD, DD);
        transpose_h_kernel<<<tD, 256>>>(Wv + (size_t)l * DD * DD, wtqkv + o5 + 2ull * DD * DD, DD, DD);
        transpose_h_kernel<<<tD, 256>>>(Wz + (size_t)l * DD * DD, wtqkv + o5 + 3ull * DD * DD, DD, DD);
        transpose_h_kernel<<<tD, 256>>>(Wr + (size_t)l * DD * DD, wtqkv + o5 + 4ull * DD * DD, DD, DD);
        transpose_h_kernel<<<tD, 256>>>(Wo + (size_t)l * DD * DD, wto + (size_t)l * DD * DD, DD, DD);
        transpose_h_kernel<<<t1, 256>>>(W1 + (size_t)l * DD * DF, wt1 + (size_t)l * DF * DD, DD, DF);
        transpose_h_kernel<<<t2, 256>>>(W2 + (size_t)l * DF * DD, wt2 + (size_t)l * DD * DF, DF, DD);
    }
    biaspack_kernel<<<(NL * QKVLD + 255) / 256, 256>>>(bq, bk, bv, bz, br, bcat);

    copy_kernel<<<eblocks, ethreads>>>(x, seq, nElem);

    dim3 gQKVZR(QKVLD / GBN, NTOK / GBM);  // (40, 32)
    dim3 gO(DD / GBN, NTOK / GBM);         // (8, 32)
    dim3 gM1(DF / GBN, NTOK / GBM);        // (32, 32)
    dim3 gFA(TT / FBM, BB * HH);           // (16, 32)

    for (int l = 0; l < NL; l++) {
        layernorm_kernel<__half><<<NTOK, 256>>>(x, ln1w + l * DD, ln1b + l * DD, xn);

        gemm_f16_kernel<<<gQKVZR, 256, GEMM_SMEM>>>(
            xn, wtqkv + (size_t)l * QKVLD * DD, bcat + l * QKVLD, qkvzr, DD, QKVLD, 0, 1);

        flash_attn_kernel<<<gFA, 256, FLASH_SMEM>>>(qkvzr, y);

        gemm_f16_kernel<<<gO, 256, GEMM_SMEM>>>(
            y, wto + (size_t)l * DD * DD, bo + l * DD, xat, DD, DD, 0, 0);
        gate1_kernel<<<eblocks, ethreads>>>(x, xat, qkvzr, zs, nElem);

        layernorm_kernel<__half><<<NTOK, 256>>>(x, ln2w + l * DD, ln2b + l * DD, xn);
        gemm_f16_kernel<<<gM1, 256, GEMM_SMEM>>>(
            xn, wt1 + (size_t)l * DF * DD, b1 + l * DF, h1, DD, DF, 1, 1);   // +GELU
        gemm_f16_kernel<<<gO, 256, GEMM_SMEM>>>(
            h1, wt2 + (size_t)l * DD * DF, b2 + l * DD, mlp, DF, DD, 0, 0);
        gate2_kernel<<<eblocks, ethreads>>>(x, mlp, zs, seq, nElem);
    }

    layernorm_kernel<float><<<NTOK, 256>>>(x, lnfw, lnfb, (float*)d_out);
}